// round 6
// baseline (speedup 1.0000x reference)
#include <cuda_runtime.h>
#include <cstdint>

#define E_CNT 3200000
#define N_CNT 100000

// ---------------- scratch ----------------------------------------------------
__device__ float g_ph[N_CNT * 52];     // per-layer: h @ Wm_h + bm (padded stride FP)
__device__ float g_acc[N_CNT * 52];    // per-layer aggregation target
__device__ float g_h1[N_CNT * 52];
__device__ float g_h2[N_CNT * 28];

__device__ __forceinline__ uint32_t f2tf32(float f) {
    uint32_t u;
    asm("cvt.rna.tf32.f32 %0, %1;" : "=r"(u) : "f"(f));
    return u;
}

__device__ __forceinline__ void mma_tf32(float c[4], uint32_t a0, uint32_t a1,
                                         uint32_t a2, uint32_t a3,
                                         uint32_t b0, uint32_t b1) {
    asm volatile(
        "mma.sync.aligned.m16n8k8.row.col.f32.tf32.tf32.f32 "
        "{%0,%1,%2,%3}, {%4,%5,%6,%7}, {%8,%9}, {%0,%1,%2,%3};"
        : "+f"(c[0]), "+f"(c[1]), "+f"(c[2]), "+f"(c[3])
        : "r"(a0), "r"(a1), "r"(a2), "r"(a3), "r"(b0), "r"(b1));
}

// ---------------- fused per-layer edge kernel --------------------------------
// acc[dst[e]] += relu( tf32(ef[e]) @ tf32(Wm_e) + ph[src[e]] )   (bias in ph)
// FOUT: real out cols; FP: padded acc/ph stride (mult of 4); NP: MMA-padded N
// (mult of 16); FIN: h-feature rows of Wm (Wm is [FIN+64][FOUT], e-rows last 64).
// Block: 256 thr = 8 warps = 4 m-warps x 2 n-warps. Warp tile 32 x NP/2.
#define SA_STRIDE 68

template<int FOUT, int FP, int NP, int FIN>
__global__ void __launch_bounds__(256, 2)
fused_edge(const float* __restrict__ ef, const int* __restrict__ src,
           const int* __restrict__ dst, const float* __restrict__ Wm) {
    constexpr int NT  = NP / 16;        // n-tiles of 8 per warp
    constexpr int SBS = NP + 4;         // B smem stride
    constexpr int SS  = NP + 4;         // stage stride (aliases sA region)
    constexpr int NV  = FP / 4;         // float4 groups per edge in scatter

    extern __shared__ char smraw[];
    uint32_t* sA    = (uint32_t*)smraw;                         // 128 x 68 u32
    float*    sStage = (float*)smraw;                           // alias: 128 x SS
    uint32_t* sB    = (uint32_t*)(smraw + 128 * SA_STRIDE * 4); // 64 x SBS
    int*      sSrc  = (int*)(smraw + 128 * SA_STRIDE * 4 + 64 * SBS * 4);
    int*      sDst  = sSrc + 128;

    int t = threadIdx.x;
    int wid = t >> 5, lane = t & 31;
    int warp_m = wid & 3, warp_n = wid >> 2;
    int lq = lane >> 2;      // 0..7
    int lr = lane & 3;       // 0..3

    // one-time B tile: sB[k][n] = tf32(Wm[(FIN+k)*FOUT + n]), zero-padded n>=FOUT
    for (int i = t; i < 64 * NP; i += 256) {
        int k = i / NP, n = i % NP;
        float w = (n < FOUT) ? Wm[(FIN + k) * FOUT + n] : 0.f;
        sB[k * SBS + n] = f2tf32(w);
    }
    __syncthreads();

    const int a_row0 = warp_m * 32 + lq;
    const int b_col0 = warp_n * (NP / 2) + lq;

    for (int tile = blockIdx.x; tile < E_CNT / 128; tile += gridDim.x) {
        // ---- load src/dst + A tile (contiguous 32KB), convert to tf32 ----
        if (t < 128) sSrc[t] = src[tile * 128 + t];
        else         sDst[t - 128] = dst[tile * 128 + (t - 128)];
        const float4* asrc = (const float4*)(ef + (size_t)tile * 128 * 64);
#pragma unroll
        for (int j = 0; j < 8; j++) {
            int i = j * 256 + t;
            int r = i >> 4, k4 = i & 15;
            float4 v = asrc[i];
            uint4 u;
            u.x = f2tf32(v.x); u.y = f2tf32(v.y);
            u.z = f2tf32(v.z); u.w = f2tf32(v.w);
            *(uint4*)&sA[r * SA_STRIDE + k4 * 4] = u;
        }
        __syncthreads();

        // ---- MMA ----
        float c[2][NT][4];
#pragma unroll
        for (int mt = 0; mt < 2; mt++)
#pragma unroll
            for (int nt = 0; nt < NT; nt++)
#pragma unroll
                for (int q = 0; q < 4; q++) c[mt][nt][q] = 0.f;

#pragma unroll
        for (int s = 0; s < 8; s++) {
            int kc = s * 8 + lr;
            uint32_t a[2][4];
#pragma unroll
            for (int mt = 0; mt < 2; mt++) {
                int r = a_row0 + mt * 16;
                a[mt][0] = sA[r * SA_STRIDE + kc];
                a[mt][1] = sA[(r + 8) * SA_STRIDE + kc];
                a[mt][2] = sA[r * SA_STRIDE + kc + 4];
                a[mt][3] = sA[(r + 8) * SA_STRIDE + kc + 4];
            }
#pragma unroll
            for (int nt = 0; nt < NT; nt++) {
                uint32_t b0 = sB[kc * SBS + b_col0 + nt * 8];
                uint32_t b1 = sB[(kc + 4) * SBS + b_col0 + nt * 8];
                mma_tf32(c[0][nt], a[0][0], a[0][1], a[0][2], a[0][3], b0, b1);
                mma_tf32(c[1][nt], a[1][0], a[1][1], a[1][2], a[1][3], b0, b1);
            }
        }
        __syncthreads();   // done reading sA; safe to overwrite with stage

        // ---- stage fragments into smem (alias of sA) ----
#pragma unroll
        for (int nt = 0; nt < NT; nt++) {
            int col = warp_n * (NP / 2) + nt * 8 + lr * 2;
#pragma unroll
            for (int mt = 0; mt < 2; mt++) {
                int row = warp_m * 32 + mt * 16 + lq;
                *(float2*)&sStage[row * SS + col] = make_float2(c[mt][nt][0], c[mt][nt][1]);
                *(float2*)&sStage[(row + 8) * SS + col] = make_float2(c[mt][nt][2], c[mt][nt][3]);
            }
        }
        __syncthreads();

        // ---- gather ph[src], relu, scatter-add to acc[dst] ----
        for (int i = t; i < 128 * NV; i += 256) {
            int e = i / NV;
            int cg = i - e * NV;
            int s = sSrc[e];
            int d = sDst[e];
            float4 pv = *(const float4*)&sStage[e * SS + cg * 4];
            const float4 hv = *(const float4*)&g_ph[(size_t)s * FP + 4 * cg];
            float x = fmaxf(pv.x + hv.x, 0.f);
            float y = fmaxf(pv.y + hv.y, 0.f);
            float z = fmaxf(pv.z + hv.z, 0.f);
            float w = fmaxf(pv.w + hv.w, 0.f);
            float* a = &g_acc[(size_t)d * FP + 4 * cg];
            asm volatile("red.global.add.v4.f32 [%0], {%1, %2, %3, %4};"
                         :: "l"(a), "f"(x), "f"(y), "f"(z), "f"(w) : "memory");
        }
        __syncthreads();   // before next tile overwrites stage/sSrc
    }
}

// ---------------- node pre-GEMM: ph = h @ Wm_h + bm; zero acc ----------------
template<int K, int F, int FP, int HS>
__global__ void node_pre(const float* __restrict__ h, const float* __restrict__ Wm,
                         const float* __restrict__ bm) {
    __shared__ float sW[K * F];
    int tid = threadIdx.y * 64 + threadIdx.x;
    for (int i = tid; i < K * F; i += 256) sW[i] = Wm[i];
    __syncthreads();
    int node = blockIdx.x * 4 + threadIdx.y;
    int tx = threadIdx.x;
    float a = 0.f;
    if (tx < F) {
        a = bm[tx];
        const float* hr = h + (size_t)node * HS;
#pragma unroll 4
        for (int k = 0; k < K; k++) a += hr[k] * sW[k * F + tx];
    }
    if (tx < FP) {
        g_ph[node * FP + tx]  = a;
        g_acc[node * FP + tx] = 0.f;
    }
}

// ---------------- node apply: h' = relu(cat(h, acc) @ Wa + ba) ---------------
template<int FH, int HS, int FN, int FNP, int FOUT, int FOUTP, int OSTR>
__global__ void node_apply(const float* __restrict__ h, const float* __restrict__ Wa,
                           const float* __restrict__ ba, float* __restrict__ out) {
    __shared__ float sW[(FH + FN) * FOUT];
    int tid = threadIdx.y * 64 + threadIdx.x;
    for (int i = tid; i < (FH + FN) * FOUT; i += 256) sW[i] = Wa[i];
    __syncthreads();
    int node = blockIdx.x * 4 + threadIdx.y;
    int tx = threadIdx.x;
    float a = 0.f;
    if (tx < FOUT) {
        a = ba[tx];
        const float* hr = h + (size_t)node * HS;
#pragma unroll 4
        for (int k = 0; k < FH; k++) a += hr[k] * sW[k * FOUT + tx];
        const float* nr = g_acc + (size_t)node * FNP;
#pragma unroll 4
        for (int k = 0; k < FN; k++) a += nr[k] * sW[(FH + k) * FOUT + tx];
        a = fmaxf(a, 0.f);
    }
    if (tx < FOUTP) out[(size_t)node * OSTR + tx] = a;
}

// ---------------- launch ------------------------------------------------------
extern "C" void kernel_launch(void* const* d_in, const int* in_sizes, int n_in,
                              void* d_out, int out_size) {
    const float* nfeats = (const float*)d_in[0];
    const float* efeats = (const float*)d_in[1];
    const int*   src    = (const int*)d_in[2];
    const int*   dst    = (const int*)d_in[3];
    const float* Wm1 = (const float*)d_in[4];  const float* bm1 = (const float*)d_in[5];
    const float* Wa1 = (const float*)d_in[6];  const float* ba1 = (const float*)d_in[7];
    const float* Wm2 = (const float*)d_in[8];  const float* bm2 = (const float*)d_in[9];
    const float* Wa2 = (const float*)d_in[10]; const float* ba2 = (const float*)d_in[11];
    const float* Wm3 = (const float*)d_in[12]; const float* bm3 = (const float*)d_in[13];
    const float* Wa3 = (const float*)d_in[14]; const float* ba3 = (const float*)d_in[15];
    float* out = (float*)d_out;

    void *h1p_, *h2p_;
    cudaGetSymbolAddress(&h1p_, g_h1);
    cudaGetSymbolAddress(&h2p_, g_h2);
    float* h1p = (float*)h1p_;
    float* h2p = (float*)h2p_;

    dim3 nb(64, 4);
    int ngrid = N_CNT / 4;

    // smem: sA(128*68*4=34816) + sB(64*(NP+4)*4) + src/dst(1024)
    constexpr int SM1 = 34816 + 64 * 68 * 4 + 1024;   // NP=64 -> 53248
    constexpr int SM2 = 34816 + 64 * 36 * 4 + 1024;   // NP=32 -> 45056

    cudaFuncSetAttribute((const void*)fused_edge<50, 52, 64, 64>,
                         cudaFuncAttributeMaxDynamicSharedMemorySize, SM1);
    cudaFuncSetAttribute((const void*)fused_edge<25, 28, 32, 50>,
                         cudaFuncAttributeMaxDynamicSharedMemorySize, SM2);
    cudaFuncSetAttribute((const void*)fused_edge<32, 32, 32, 25>,
                         cudaFuncAttributeMaxDynamicSharedMemorySize, SM2);

    // ---- layer 1 ----
    node_pre<64, 50, 52, 64><<<ngrid, nb>>>(nfeats, Wm1, bm1);
    fused_edge<50, 52, 64, 64><<<296, 256, SM1>>>(efeats, src, dst, Wm1);
    node_apply<64, 64, 50, 52, 50, 52, 52><<<ngrid, nb>>>(nfeats, Wa1, ba1, h1p);

    // ---- layer 2 ----
    node_pre<50, 25, 28, 52><<<ngrid, nb>>>(h1p, Wm2, bm2);
    fused_edge<25, 28, 32, 50><<<296, 256, SM2>>>(efeats, src, dst, Wm2);
    node_apply<50, 52, 25, 28, 25, 28, 28><<<ngrid, nb>>>(h1p, Wa2, ba2, h2p);

    // ---- layer 3 ----
    node_pre<25, 32, 32, 28><<<ngrid, nb>>>(h2p, Wm3, bm3);
    fused_edge<32, 32, 32, 25><<<296, 256, SM2>>>(efeats, src, dst, Wm3);
    node_apply<25, 28, 32, 32, 32, 32, 32><<<ngrid, nb>>>(h2p, Wa3, ba3, out);
}